// round 6
// baseline (speedup 1.0000x reference)
#include <cuda_runtime.h>
#include <math.h>

#define EPS 1e-6f
#define COLS 128
#define ROWS 16

__device__ float4 g_plane[4096];

// Plane (n,d) per triangle; also sets the output diagonal to 1.
__global__ void prep_kernel(const float* __restrict__ T,
                            float* __restrict__ out, int N) {
    int i = blockIdx.x * blockDim.x + threadIdx.x;
    if (i >= N) return;
    const float* t = T + (size_t)i * 9;
    float v0x = t[0], v0y = t[1], v0z = t[2];
    float e1x = t[3] - v0x, e1y = t[4] - v0y, e1z = t[5] - v0z;
    float e2x = t[6] - v0x, e2y = t[7] - v0y, e2z = t[8] - v0z;
    float nx = e1y * e2z - e1z * e2y;
    float ny = e1z * e2x - e1x * e2z;
    float nz = e1x * e2y - e1y * e2x;
    float d = -(nx * v0x + ny * v0y + nz * v0z);
    g_plane[i] = make_float4(nx, ny, nz, d);
    out[(size_t)i * N + i] = 1.0f;
}

// Interval endpoints from sign predicates + snapped distances.
// valid_k == (di*dj<=0) & !(di==0 & dj==0) for snapped d (|d|>=EPS or 0).
// valid => di != dj, so the divide needs no guard.
__device__ __forceinline__ void interval3(const float p[3], const float d[3],
                                          const bool pp[3], const bool nn[3],
                                          float& tmin, float& tmax) {
    tmin = INFINITY;
    tmax = -INFINITY;
#pragma unroll
    for (int k = 0; k < 3; k++) {
        const int kn = (k == 2) ? 0 : k + 1;
        bool valid = !((pp[k] & pp[kn]) | (nn[k] & nn[kn])) &
                     (pp[k] | nn[k] | pp[kn] | nn[kn]);
        float t = p[k] + (p[kn] - p[k]) * __fdividef(d[k], d[k] - d[kn]);
        if (valid) {
            tmin = fminf(tmin, t);
            tmax = fmaxf(tmax, t);
        }
    }
}

__device__ __forceinline__ float sel3(int ax, float x, float y, float z) {
    return (ax == 0) ? x : ((ax == 1) ? y : z);
}

// Thread owns column j (triangle B in registers); loops over ROWS rows i
// staged in shared. Writes 1.0 to both mirror cells on intersection only.
__global__ __launch_bounds__(COLS) void pair_kernel(const float* __restrict__ T,
                                                    float* __restrict__ out,
                                                    int N) {
    const int c0 = blockIdx.x * COLS;
    const int r0 = blockIdx.y * ROWS;
    if (r0 + 1 >= c0 + COLS) return;  // no i<j pairs in this block

    __shared__ float sA[ROWS][9];
    __shared__ float4 sP[ROWS];

    const int tid = threadIdx.x;
    for (int q = tid; q < ROWS * 9; q += COLS) {
        int r = q / 9, c = q % 9;
        int gi = r0 + r;
        sA[r][c] = (gi < N) ? T[(size_t)gi * 9 + c] : 0.0f;
    }
    if (tid < ROWS) {
        int gi = r0 + tid;
        sP[tid] = (gi < N) ? g_plane[gi] : make_float4(0, 0, 0, 1);
    }

    const int j = c0 + tid;
    const bool jok = j < N;
    const int jc = jok ? j : (N - 1);

    // Register-resident column triangle + plane.
    float B[9];
    const float* tb = T + (size_t)jc * 9;
#pragma unroll
    for (int c = 0; c < 9; c++) B[c] = tb[c];
    const float4 nb = g_plane[jc];

    __syncthreads();

    for (int r = 0; r < ROWS; r++) {
        const int i = r0 + r;
        const float* A = sA[r];        // warp-uniform broadcast reads
        const float4 na = sP[r];

        // Signed distances with EPS snap + sign predicates.
        float dv[3], du[3];
        bool pv_[3], nv_[3], pu_[3], nu_[3];
#pragma unroll
        for (int v = 0; v < 3; v++) {
            float dd = A[3 * v] * nb.x + A[3 * v + 1] * nb.y +
                       A[3 * v + 2] * nb.z + nb.w;
            dd = (fabsf(dd) < EPS) ? 0.0f : dd;
            dv[v] = dd;
            pv_[v] = dd > 0.0f;
            nv_[v] = dd < 0.0f;
            float ee = B[3 * v] * na.x + B[3 * v + 1] * na.y +
                       B[3 * v + 2] * na.z + na.w;
            ee = (fabsf(ee) < EPS) ? 0.0f : ee;
            du[v] = ee;
            pu_[v] = ee > 0.0f;
            nu_[v] = ee < 0.0f;
        }

        bool ssv = (pv_[0] & pv_[1] & pv_[2]) | (nv_[0] & nv_[1] & nv_[2]);
        bool ssu = (pu_[0] & pu_[1] & pu_[2]) | (nu_[0] & nu_[1] & nu_[2]);

        // Dominant axis of na x nb (first-max argmax).
        float Dx = na.y * nb.z - na.z * nb.y;
        float Dy = na.z * nb.x - na.x * nb.z;
        float Dz = na.x * nb.y - na.y * nb.x;
        int ax = 0;
        float m = fabsf(Dx);
        if (fabsf(Dy) > m) { ax = 1; m = fabsf(Dy); }
        if (fabsf(Dz) > m) { ax = 2; }

        float pv[3], pu[3];
#pragma unroll
        for (int v = 0; v < 3; v++) {
            pv[v] = A[3 * v + ax];                         // 3-addr multicast LDS
            pu[v] = sel3(ax, B[3 * v], B[3 * v + 1], B[3 * v + 2]);
        }

        float t0v, t1v, t0u, t1u;
        interval3(pv, dv, pv_, nv_, t0v, t1v);
        interval3(pu, du, pu_, nu_, t0u, t1u);
        bool hit = !ssv & !ssu &
                   (fmaxf(t0v, t0u) <= fminf(t1v, t1u));

        if (hit & (i < j) & jok) {
            out[(size_t)i * N + j] = 1.0f;
            out[(size_t)j * N + i] = 1.0f;
        }
    }
}

extern "C" void kernel_launch(void* const* d_in, const int* in_sizes, int n_in,
                              void* d_out, int out_size) {
    const float* T = (const float*)d_in[0];
    float* out = (float*)d_out;
    int N = in_sizes[0] / 9;

    cudaMemsetAsync(d_out, 0, (size_t)out_size * sizeof(float), 0);
    prep_kernel<<<(N + 255) / 256, 256>>>(T, out, N);

    dim3 grd((N + COLS - 1) / COLS, (N + ROWS - 1) / ROWS);
    pair_kernel<<<grd, COLS>>>(T, out, N);
}

// round 7
// speedup vs baseline: 1.2141x; 1.2141x over previous
#include <cuda_runtime.h>
#include <math.h>

#define EPS 1e-6f
#define COLS 128
#define ROWS 8

// Interval endpoints from sign predicates + snapped distances.
// valid_k == (di*dj<=0) & !(di==0 & dj==0) for snapped d (|d|>=EPS or 0).
// valid => di != dj, so the divide needs no guard.
__device__ __forceinline__ void interval3(const float p[3], const float d[3],
                                          const bool pp[3], const bool nn[3],
                                          float& tmin, float& tmax) {
    tmin = INFINITY;
    tmax = -INFINITY;
#pragma unroll
    for (int k = 0; k < 3; k++) {
        const int kn = (k == 2) ? 0 : k + 1;
        bool valid = !((pp[k] & pp[kn]) | (nn[k] & nn[kn])) &
                     (pp[k] | nn[k] | pp[kn] | nn[kn]);
        float t = p[k] + (p[kn] - p[k]) * __fdividef(d[k], d[k] - d[kn]);
        if (valid) {
            tmin = fminf(tmin, t);
            tmax = fmaxf(tmax, t);
        }
    }
}

__device__ __forceinline__ float sel3(int ax, float x, float y, float z) {
    return (ax == 0) ? x : ((ax == 1) ? y : z);
}

// One thread = one column j. B triangle + plane in registers. ROWS rows
// staged in shared. Direct stores (i<=j) coalesced per row; mirror stores
// (i<j) per-thread into row j. Full matrix covered with no zero-fill pass.
__global__ __launch_bounds__(COLS, 12)
void pair_kernel(const float* __restrict__ T, float* __restrict__ out, int N) {
    const int c0 = blockIdx.x * COLS;
    const int r0 = blockIdx.y * ROWS;
    if (r0 > c0 + COLS - 1) return;  // tile entirely below diagonal

    __shared__ float sA[ROWS][9];
    __shared__ float4 sP[ROWS];

    const int tid = threadIdx.x;

    // Stage row triangles.
    for (int q = tid; q < ROWS * 9; q += COLS) {
        int r = q / 9, c = q % 9;
        int gi = r0 + r;
        sA[r][c] = (gi < N) ? T[(size_t)gi * 9 + c] : 0.0f;
    }
    __syncthreads();
    // Row planes from staged data.
    if (tid < ROWS) {
        const float* t = sA[tid];
        float e1x = t[3] - t[0], e1y = t[4] - t[1], e1z = t[5] - t[2];
        float e2x = t[6] - t[0], e2y = t[7] - t[1], e2z = t[8] - t[2];
        float nx = e1y * e2z - e1z * e2y;
        float ny = e1z * e2x - e1x * e2z;
        float nz = e1x * e2y - e1y * e2x;
        sP[tid] = make_float4(nx, ny, nz, -(nx * t[0] + ny * t[1] + nz * t[2]));
    }

    const int j = c0 + tid;
    const bool jok = j < N;
    const int jc = jok ? j : (N - 1);

    // Column triangle + its plane in registers.
    float B[9];
    const float* tb = T + (size_t)jc * 9;
#pragma unroll
    for (int c = 0; c < 9; c++) B[c] = __ldg(tb + c);
    float4 nb;
    {
        float e1x = B[3] - B[0], e1y = B[4] - B[1], e1z = B[5] - B[2];
        float e2x = B[6] - B[0], e2y = B[7] - B[1], e2z = B[8] - B[2];
        nb.x = e1y * e2z - e1z * e2y;
        nb.y = e1z * e2x - e1x * e2z;
        nb.z = e1x * e2y - e1y * e2x;
        nb.w = -(nb.x * B[0] + nb.y * B[1] + nb.z * B[2]);
    }
    __syncthreads();

#pragma unroll
    for (int r = 0; r < ROWS; r++) {
        const int i = r0 + r;
        const float* A = sA[r];    // warp-uniform broadcast LDS
        const float4 na = sP[r];

        float dv[3], du[3];
        bool pv_[3], nv_[3], pu_[3], nu_[3];
#pragma unroll
        for (int v = 0; v < 3; v++) {
            float dd = A[3 * v] * nb.x + A[3 * v + 1] * nb.y +
                       A[3 * v + 2] * nb.z + nb.w;
            dd = (fabsf(dd) < EPS) ? 0.0f : dd;
            dv[v] = dd;
            pv_[v] = dd > 0.0f;
            nv_[v] = dd < 0.0f;
            float ee = B[3 * v] * na.x + B[3 * v + 1] * na.y +
                       B[3 * v + 2] * na.z + na.w;
            ee = (fabsf(ee) < EPS) ? 0.0f : ee;
            du[v] = ee;
            pu_[v] = ee > 0.0f;
            nu_[v] = ee < 0.0f;
        }

        bool ssv = (pv_[0] & pv_[1] & pv_[2]) | (nv_[0] & nv_[1] & nv_[2]);
        bool ssu = (pu_[0] & pu_[1] & pu_[2]) | (nu_[0] & nu_[1] & nu_[2]);

        // Dominant axis of na x nb (first-max argmax).
        float Dx = na.y * nb.z - na.z * nb.y;
        float Dy = na.z * nb.x - na.x * nb.z;
        float Dz = na.x * nb.y - na.y * nb.x;
        int ax = 0;
        float m = fabsf(Dx);
        if (fabsf(Dy) > m) { ax = 1; m = fabsf(Dy); }
        if (fabsf(Dz) > m) { ax = 2; }

        float pv[3], pu[3];
#pragma unroll
        for (int v = 0; v < 3; v++) {
            pv[v] = A[3 * v + ax];
            pu[v] = sel3(ax, B[3 * v], B[3 * v + 1], B[3 * v + 2]);
        }

        float t0v, t1v, t0u, t1u;
        interval3(pv, dv, pv_, nv_, t0v, t1v);
        interval3(pu, du, pu_, nu_, t0u, t1u);
        bool hit = !ssv & !ssu & (fmaxf(t0v, t0u) <= fminf(t1v, t1u));

        float val = (i == j) ? 1.0f : (hit ? 1.0f : 0.0f);
        // Direct (upper + diagonal) store: coalesced across the warp.
        if (jok & (i <= j) & (i < N)) out[(size_t)i * N + j] = val;
        // Mirror (lower) store.
        if (jok & (i < j) & (i < N)) out[(size_t)j * N + i] = val;
    }
}

extern "C" void kernel_launch(void* const* d_in, const int* in_sizes, int n_in,
                              void* d_out, int out_size) {
    const float* T = (const float*)d_in[0];
    float* out = (float*)d_out;
    int N = in_sizes[0] / 9;

    dim3 grd((N + COLS - 1) / COLS, (N + ROWS - 1) / ROWS);
    pair_kernel<<<grd, COLS>>>(T, out, N);
}